// round 10
// baseline (speedup 1.0000x reference)
#include <cuda_runtime.h>
#include <cuda_fp16.h>
#include <math_constants.h>
#include <cstdint>

#define Bsz 8
#define T   2048
#define C   1024
#define H   128
#define NROWS (Bsz * T)

// -------- gmem scratch (16B aligned) --------
__device__ __align__(16) __half g_xh[NROWS * C];
__device__ __align__(16) __half g_xl[NROWS * C];
__device__ __align__(16) __half g_wth[3 * H * C];
__device__ __align__(16) __half g_wtl[3 * H * C];
__device__ __align__(16) __half g_qh[NROWS * H];
__device__ __align__(16) __half g_ql[NROWS * H];
__device__ __align__(16) __half g_kh[NROWS * H];
__device__ __align__(16) __half g_kl[NROWS * H];
__device__ __align__(16) __half g_vth[Bsz * H * T];
__device__ __align__(16) __half g_vtl[Bsz * H * T];

// -------- helpers --------
__device__ __forceinline__ void mma16816(float* c, const unsigned* a, const unsigned* b) {
    asm volatile(
        "mma.sync.aligned.m16n8k16.row.col.f32.f16.f16.f32 "
        "{%0,%1,%2,%3}, {%4,%5,%6,%7}, {%8,%9}, {%0,%1,%2,%3};"
        : "+f"(c[0]), "+f"(c[1]), "+f"(c[2]), "+f"(c[3])
        : "r"(a[0]), "r"(a[1]), "r"(a[2]), "r"(a[3]), "r"(b[0]), "r"(b[1]));
}
__device__ __forceinline__ void ldsm4(unsigned* r, uint32_t addr) {
    asm volatile("ldmatrix.sync.aligned.m8n8.x4.shared.b16 {%0,%1,%2,%3}, [%4];"
        : "=r"(r[0]), "=r"(r[1]), "=r"(r[2]), "=r"(r[3]) : "r"(addr));
}
__device__ __forceinline__ unsigned h2u(float x, float y) {
    __half2 h = __floats2half2_rn(x, y);
    return *reinterpret_cast<unsigned*>(&h);
}
__device__ __forceinline__ unsigned h2lo(float x, float y, unsigned hi) {
    __half2 h = *reinterpret_cast<__half2*>(&hi);
    float2 f = __half22float2(h);
    __half2 l = __floats2half2_rn(x - f.x, y - f.y);
    return *reinterpret_cast<unsigned*>(&l);
}
__device__ __forceinline__ void cpa16(uint32_t dst, const void* src) {
    asm volatile("cp.async.cg.shared.global [%0], [%1], 16;" :: "r"(dst), "l"(src));
}
#define CP_COMMIT() asm volatile("cp.async.commit_group;" ::: "memory")
#define CP_WAIT0()  asm volatile("cp.async.wait_group 0;" ::: "memory")

// ============================================================
// split_kernel: x (fp32) -> half hi/lo
// ============================================================
__global__ __launch_bounds__(256) void split_kernel(const float* __restrict__ x)
{
    const int tid = threadIdx.x;
#pragma unroll
    for (int i = 0; i < 4; i++) {
        unsigned u = blockIdx.x * 1024 + i * 256 + tid;
        float4 v = ((const float4*)x)[u];
        unsigned h0 = h2u(v.x, v.y), h1 = h2u(v.z, v.w);
        unsigned l0 = h2lo(v.x, v.y, h0), l1 = h2lo(v.z, v.w, h1);
        ((uint2*)g_xh)[u] = make_uint2(h0, h1);
        ((uint2*)g_xl)[u] = make_uint2(l0, l1);
    }
}

// ============================================================
// wsplit_kernel: W[k][n] -> W^T hi/lo [sel][n][k]
// ============================================================
__global__ __launch_bounds__(256) void wsplit_kernel(
    const float* __restrict__ Wk, const float* __restrict__ Wq,
    const float* __restrict__ Wv)
{
    __shared__ float ws[32][133];
    const int sel = blockIdx.x;
    const float* W = (sel == 0) ? Wk : (sel == 1) ? Wq : Wv;
    const int k0 = blockIdx.y * 32;
    const int tid = threadIdx.x;
#pragma unroll
    for (int i = 0; i < 16; i++) {
        int idx = tid + i * 256;
        int k = idx >> 7, n = idx & 127;
        ws[k][n] = W[(size_t)(k0 + k) * H + n];
    }
    __syncthreads();
    __half* wth = g_wth + (size_t)sel * H * C;
    __half* wtl = g_wtl + (size_t)sel * H * C;
#pragma unroll
    for (int i = 0; i < 16; i++) {
        int idx = tid + i * 256;
        int n = idx >> 5, kk = idx & 31;
        float v = ws[kk][n];
        __half h = __float2half_rn(v);
        wth[(size_t)n * C + k0 + kk] = h;
        wtl[(size_t)n * C + k0 + kk] = __float2half_rn(v - __half2float(h));
    }
}

// ============================================================
// Projection GEMM (HMMA fp16x3), cp.async double-buffered, ldmatrix feeds.
// ============================================================
#define PB_ARR 10240            // bytes per array tile (128 x 40 halves, 80B rows)
#define PB_SZ  40960
#define SMEM_PROJ 81920

__global__ __launch_bounds__(256, 2) void proj_kernel()
{
    extern __shared__ char smem[];
    const uint32_t sbase = (uint32_t)__cvta_generic_to_shared(smem);

    const int sel = blockIdx.x;
    const int m0 = blockIdx.y * 128;
    const int tid = threadIdx.x;
    const int w = tid >> 5, lane = tid & 31;
    const int wm = w & 3, wn = w >> 2;
    const int g = lane >> 2, t = lane & 3;
    const int lrow16 = lane & 15;            // ldmatrix row-within-16
    const int lcol8  = (lane >> 4) << 3;     // ldmatrix col half (0 or 8)

    const __half* src[4] = {
        g_xh + (size_t)m0 * C, g_xl + (size_t)m0 * C,
        g_wth + (size_t)sel * H * C, g_wtl + (size_t)sel * H * C };

    int larr[8], lrow[8], lc8[8];
#pragma unroll
    for (int i = 0; i < 8; i++) {
        int idx = tid + i * 256;
        larr[i] = idx >> 9;
        int j = idx & 511;
        lrow[i] = j >> 2;
        lc8[i]  = (j & 3) * 8;
    }

#pragma unroll
    for (int i = 0; i < 8; i++)
        cpa16(sbase + larr[i] * PB_ARR + lrow[i] * 80 + lc8[i] * 2,
              src[larr[i]] + (size_t)lrow[i] * C + lc8[i]);
    CP_COMMIT();

    float c[2][8][4];
#pragma unroll
    for (int mt = 0; mt < 2; mt++)
#pragma unroll
        for (int j = 0; j < 8; j++)
#pragma unroll
            for (int e = 0; e < 4; e++) c[mt][j][e] = 0.f;

    for (int ks = 0; ks < 32; ks++) {
        CP_WAIT0();
        __syncthreads();
        const uint32_t bb = sbase + (ks & 1) * PB_SZ;
        if (ks < 31) {
            const uint32_t db = sbase + ((ks + 1) & 1) * PB_SZ;
            const int k1 = (ks + 1) * 32;
#pragma unroll
            for (int i = 0; i < 8; i++)
                cpa16(db + larr[i] * PB_ARR + lrow[i] * 80 + lc8[i] * 2,
                      src[larr[i]] + (size_t)lrow[i] * C + k1 + lc8[i]);
            CP_COMMIT();
        }

#pragma unroll
        for (int kk = 0; kk < 2; kk++) {
            const uint32_t coff = kk * 32 + lcol8 * 2;
            unsigned ah[2][4], al[2][4];
#pragma unroll
            for (int mt = 0; mt < 2; mt++) {
                uint32_t ra = bb + (wm * 32 + mt * 16 + lrow16) * 80 + coff;
                ldsm4(ah[mt], ra);
                ldsm4(al[mt], ra + PB_ARR);
            }
#pragma unroll
            for (int jp = 0; jp < 4; jp++) {
                unsigned b4h[4], b4l[4];
                uint32_t rb = bb + 2 * PB_ARR + (wn * 64 + jp * 16 + lrow16) * 80 + coff;
                ldsm4(b4h, rb);
                ldsm4(b4l, rb + PB_ARR);
                unsigned bh0[2] = { b4h[0], b4h[2] }, bh1[2] = { b4h[1], b4h[3] };
                unsigned bl0[2] = { b4l[0], b4l[2] }, bl1[2] = { b4l[1], b4l[3] };
#pragma unroll
                for (int mt = 0; mt < 2; mt++) {
                    mma16816(c[mt][2 * jp],     ah[mt], bh0);
                    mma16816(c[mt][2 * jp],     ah[mt], bl0);
                    mma16816(c[mt][2 * jp],     al[mt], bh0);
                    mma16816(c[mt][2 * jp + 1], ah[mt], bh1);
                    mma16816(c[mt][2 * jp + 1], ah[mt], bl1);
                    mma16816(c[mt][2 * jp + 1], al[mt], bh1);
                }
            }
        }
    }

    // ---- fused split epilogue
    if (sel == 2) {
#pragma unroll
        for (int mt = 0; mt < 2; mt++)
#pragma unroll
            for (int j = 0; j < 8; j++) {
                int row0 = m0 + wm * 32 + mt * 16 + g;
                int col = wn * 64 + j * 8 + 2 * t;
#pragma unroll
                for (int e = 0; e < 4; e++) {
                    int row = row0 + (e >> 1) * 8;
                    int n = col + (e & 1);
                    float val = c[mt][j][e];
                    __half h = __float2half_rn(val);
                    size_t a = ((size_t)(row >> 11) * H + n) * T + (row & 2047);
                    g_vth[a] = h;
                    g_vtl[a] = __float2half_rn(val - __half2float(h));
                }
            }
    } else {
        __half* ghi = (sel == 0) ? g_kh : g_qh;
        __half* glo = (sel == 0) ? g_kl : g_ql;
        const float sc = (sel == 1) ? 32.f : 1.f;
#pragma unroll
        for (int mt = 0; mt < 2; mt++)
#pragma unroll
            for (int j = 0; j < 8; j++) {
                int row0 = m0 + wm * 32 + mt * 16 + g;
                int col = wn * 64 + j * 8 + 2 * t;
#pragma unroll
                for (int hr = 0; hr < 2; hr++) {
                    int row = row0 + hr * 8;
                    float v0 = c[mt][j][hr * 2] * sc;
                    float v1 = c[mt][j][hr * 2 + 1] * sc;
                    unsigned hi = h2u(v0, v1);
                    unsigned lo = h2lo(v0, v1, hi);
                    *(unsigned*)(ghi + (size_t)row * H + col) = hi;
                    *(unsigned*)(glo + (size_t)row * H + col) = lo;
                }
            }
    }
}

// ============================================================
// Flash attention (HMMA fp16x3), causal, warp-local split-K softmax,
// cp.async double-buffered KV, ldmatrix operand feeds.
// ============================================================
#define A_QH   0
#define A_QL   17408
#define A_KV0  34816
#define KV_KH  0
#define KV_KL  17408
#define KV_VTH 34816
#define KV_VTL 53248
#define KV_SZ  71680
#define A_PM   178176
#define A_PL   178688
#define SMEM_ATTN 179200

__global__ __launch_bounds__(256, 1) void attn_kernel(float* __restrict__ out)
{
    extern __shared__ char smem[];
    const uint32_t sbase = (uint32_t)__cvta_generic_to_shared(smem);

    const int tid = threadIdx.x;
    const int w = tid >> 5, lane = tid & 31;
    const int wm = w & 3, wn = w >> 2;
    const int g = lane >> 2, t = lane & 3;
    const int lrow16 = lane & 15;
    const int lcol8  = (lane >> 4) << 3;
    const int bx = blockIdx.x;
    const int b = bx & 7;
    const int qt = 31 - (bx >> 3);          // LPT

    const __half* QHg = g_qh + ((size_t)b * T + (size_t)qt * 64) * H;
    const __half* QLg = g_ql + ((size_t)b * T + (size_t)qt * 64) * H;
    const __half* KHg = g_kh + (size_t)b * T * H;
    const __half* KLg = g_kl + (size_t)b * T * H;
    const __half* VHg = g_vth + (size_t)b * H * T;
    const __half* VLg = g_vtl + (size_t)b * H * T;

    // ---- prologue: Q + KV tile 0 via cp.async
#pragma unroll
    for (int i = 0; i < 4; i++) {
        int idx = tid + i * 256;
        int row = idx >> 4, c8 = (idx & 15) * 8;
        cpa16(sbase + A_QH + row * 272 + c8 * 2, QHg + (size_t)row * H + c8);
        cpa16(sbase + A_QL + row * 272 + c8 * 2, QLg + (size_t)row * H + c8);
    }
    {
        const uint32_t kb = sbase + A_KV0;
#pragma unroll
        for (int i = 0; i < 4; i++) {
            int idx = tid + i * 256;
            int row = idx >> 4, c8 = (idx & 15) * 8;
            cpa16(kb + KV_KH + row * 272 + c8 * 2, KHg + (size_t)row * H + c8);
            cpa16(kb + KV_KL + row * 272 + c8 * 2, KLg + (size_t)row * H + c8);
            int vr = idx >> 3, v8 = (idx & 7) * 8;
            cpa16(kb + KV_VTH + vr * 144 + v8 * 2, VHg + (size_t)vr * T + v8);
            cpa16(kb + KV_VTL + vr * 144 + v8 * 2, VLg + (size_t)vr * T + v8);
        }
    }
    CP_COMMIT();

    // ldmatrix base addresses (per thread, fixed)
    const uint32_t qA = sbase + A_QH + (wm * 16 + lrow16) * 272 + lcol8 * 2;

    const int r0 = wm * 16 + g, r1 = r0 + 8;
    float m[2] = {-1e30f, -1e30f}, l[2] = {0.f, 0.f};
    float o[16][4];
#pragma unroll
    for (int j = 0; j < 16; j++)
#pragma unroll
        for (int e = 0; e < 4; e++) o[j][e] = 0.f;

    for (int kt = 0; kt <= qt; kt++) {
        CP_WAIT0();
        __syncthreads();
        const uint32_t kvb = sbase + A_KV0 + (kt & 1) * KV_SZ;
        if (kt < qt) {
            const uint32_t kb = sbase + A_KV0 + ((kt + 1) & 1) * KV_SZ;
            const size_t koff = (size_t)(kt + 1) * 64;
#pragma unroll
            for (int i = 0; i < 4; i++) {
                int idx = tid + i * 256;
                int row = idx >> 4, c8 = (idx & 15) * 8;
                cpa16(kb + KV_KH + row * 272 + c8 * 2, KHg + (koff + row) * H + c8);
                cpa16(kb + KV_KL + row * 272 + c8 * 2, KLg + (koff + row) * H + c8);
                int vr = idx >> 3, v8 = (idx & 7) * 8;
                cpa16(kb + KV_VTH + vr * 144 + v8 * 2, VHg + (size_t)vr * T + koff + v8);
                cpa16(kb + KV_VTL + vr * 144 + v8 * 2, VLg + (size_t)vr * T + koff + v8);
            }
            CP_COMMIT();
        }

        // ---- S = Q K^T (3-pass), ldmatrix feeds
        float s[4][4];
#pragma unroll
        for (int j = 0; j < 4; j++)
#pragma unroll
            for (int e = 0; e < 4; e++) s[j][e] = 0.f;

        const uint32_t kB = kvb + KV_KH + (wn * 32 + lrow16) * 272 + lcol8 * 2;
#pragma unroll
        for (int kk = 0; kk < 8; kk++) {
            unsigned ah[4], al[4];
            ldsm4(ah, qA + kk * 32);
            ldsm4(al, qA + kk * 32 + (A_QL - A_QH));
#pragma unroll
            for (int jp = 0; jp < 2; jp++) {
                unsigned b4h[4], b4l[4];
                uint32_t rb = kB + jp * 16 * 272 + kk * 32;
                ldsm4(b4h, rb);
                ldsm4(b4l, rb + (KV_KL - KV_KH));
                unsigned bh0[2] = { b4h[0], b4h[2] }, bh1[2] = { b4h[1], b4h[3] };
                unsigned bl0[2] = { b4l[0], b4l[2] }, bl1[2] = { b4l[1], b4l[3] };
                mma16816(s[2 * jp],     ah, bh0);
                mma16816(s[2 * jp],     ah, bl0);
                mma16816(s[2 * jp],     al, bh0);
                mma16816(s[2 * jp + 1], ah, bh1);
                mma16816(s[2 * jp + 1], ah, bl1);
                mma16816(s[2 * jp + 1], al, bh1);
            }
        }

        if (kt == qt) {
#pragma unroll
            for (int j = 0; j < 4; j++) {
                int cl = wn * 32 + j * 8 + 2 * t;
                if (cl     > r0) s[j][0] = -3e38f;
                if (cl + 1 > r0) s[j][1] = -3e38f;
                if (cl     > r1) s[j][2] = -3e38f;
                if (cl + 1 > r1) s[j][3] = -3e38f;
            }
        }

        // ---- warp-local online softmax
        float mx0 = -3e38f, mx1 = -3e38f;
#pragma unroll
        for (int j = 0; j < 4; j++) {
            mx0 = fmaxf(mx0, fmaxf(s[j][0], s[j][1]));
            mx1 = fmaxf(mx1, fmaxf(s[j][2], s[j][3]));
        }
        mx0 = fmaxf(mx0, __shfl_xor_sync(0xFFFFFFFFu, mx0, 1));
        mx0 = fmaxf(mx0, __shfl_xor_sync(0xFFFFFFFFu, mx0, 2));
        mx1 = fmaxf(mx1, __shfl_xor_sync(0xFFFFFFFFu, mx1, 1));
        mx1 = fmaxf(mx1, __shfl_xor_sync(0xFFFFFFFFu, mx1, 2));

        float mn0 = fmaxf(m[0], mx0);
        float mn1 = fmaxf(m[1], mx1);
        float al0 = __expf(m[0] - mn0);
        float al1 = __expf(m[1] - mn1);

        float sum0 = 0.f, sum1 = 0.f;
#pragma unroll
        for (int j = 0; j < 4; j++) {
            s[j][0] = __expf(s[j][0] - mn0);
            s[j][1] = __expf(s[j][1] - mn0);
            s[j][2] = __expf(s[j][2] - mn1);
            s[j][3] = __expf(s[j][3] - mn1);
            sum0 += s[j][0] + s[j][1];
            sum1 += s[j][2] + s[j][3];
        }
        sum0 += __shfl_xor_sync(0xFFFFFFFFu, sum0, 1);
        sum0 += __shfl_xor_sync(0xFFFFFFFFu, sum0, 2);
        sum1 += __shfl_xor_sync(0xFFFFFFFFu, sum1, 1);
        sum1 += __shfl_xor_sync(0xFFFFFFFFu, sum1, 2);

        l[0] = l[0] * al0 + sum0;
        l[1] = l[1] * al1 + sum1;
        m[0] = mn0; m[1] = mn1;

#pragma unroll
        for (int j = 0; j < 16; j++) {
            o[j][0] *= al0; o[j][1] *= al0;
            o[j][2] *= al1; o[j][3] *= al1;
        }
        // ---- O += P V (3-pass), ldmatrix V feeds
#pragma unroll
        for (int kk2 = 0; kk2 < 2; kk2++) {
            unsigned aph[4], apl[4];
            aph[0] = h2u(s[2*kk2][0], s[2*kk2][1]);
            aph[1] = h2u(s[2*kk2][2], s[2*kk2][3]);
            aph[2] = h2u(s[2*kk2+1][0], s[2*kk2+1][1]);
            aph[3] = h2u(s[2*kk2+1][2], s[2*kk2+1][3]);
            apl[0] = h2lo(s[2*kk2][0], s[2*kk2][1], aph[0]);
            apl[1] = h2lo(s[2*kk2][2], s[2*kk2][3], aph[1]);
            apl[2] = h2lo(s[2*kk2+1][0], s[2*kk2+1][1], aph[2]);
            apl[3] = h2lo(s[2*kk2+1][2], s[2*kk2+1][3], aph[3]);
            const uint32_t vB = kvb + KV_VTH + lrow16 * 144
                              + (wn * 32 + kk2 * 16 + lcol8) * 2;
#pragma unroll
            for (int j2p = 0; j2p < 8; j2p++) {
                unsigned v4h[4], v4l[4];
                uint32_t rv = vB + j2p * 16 * 144;
                ldsm4(v4h, rv);
                ldsm4(v4l, rv + (KV_VTL - KV_VTH));
                unsigned vh0[2] = { v4h[0], v4h[2] }, vh1[2] = { v4h[1], v4h[3] };
                unsigned vl0[2] = { v4l[0], v4l[2] }, vl1[2] = { v4l[1], v4l[3] };
                mma16816(o[2 * j2p],     aph, vh0);
                mma16816(o[2 * j2p],     aph, vl0);
                mma16816(o[2 * j2p],     apl, vh0);
                mma16816(o[2 * j2p + 1], aph, vh1);
                mma16816(o[2 * j2p + 1], aph, vl1);
                mma16816(o[2 * j2p + 1], apl, vh1);
            }
        }
    }

    // ---- final split-K combine across the two wn halves
    float* pm = (float*)(smem + A_PM);
    float* pl = (float*)(smem + A_PL);
    __syncthreads();
    if (t == 0) {
        pm[wn * 64 + r0] = m[0]; pm[wn * 64 + r1] = m[1];
        pl[wn * 64 + r0] = l[0]; pl[wn * 64 + r1] = l[1];
    }
    __syncthreads();
    float M0 = fmaxf(pm[r0], pm[64 + r0]);
    float M1 = fmaxf(pm[r1], pm[64 + r1]);
    float L0 = pl[r0] * __expf(pm[r0] - M0) + pl[64 + r0] * __expf(pm[64 + r0] - M0);
    float L1 = pl[r1] * __expf(pm[r1] - M1) + pl[64 + r1] * __expf(pm[64 + r1] - M1);
    float c0 = __expf(m[0] - M0);
    float c1 = __expf(m[1] - M1);

    float (*Ocomb)[132] = (float(*)[132])(smem + A_QH);
    if (wn == 1) {
#pragma unroll
        for (int j2 = 0; j2 < 16; j2++) {
            int col = j2 * 8 + 2 * t;
            *(float2*)&Ocomb[r0][col] = make_float2(o[j2][0] * c0, o[j2][1] * c0);
            *(float2*)&Ocomb[r1][col] = make_float2(o[j2][2] * c1, o[j2][3] * c1);
        }
    }
    __syncthreads();
    if (wn == 0) {
        const float inv0 = 1.f / L0, inv1 = 1.f / L1;
        float* out0 = out + ((size_t)b * T + (size_t)qt * 64 + r0) * H;
        float* out1 = out + ((size_t)b * T + (size_t)qt * 64 + r1) * H;
#pragma unroll
        for (int j2 = 0; j2 < 16; j2++) {
            int col = j2 * 8 + 2 * t;
            *(float2*)(out0 + col) = make_float2((o[j2][0] * c0 + Ocomb[r0][col])     * inv0,
                                                 (o[j2][1] * c0 + Ocomb[r0][col + 1]) * inv0);
            *(float2*)(out1 + col) = make_float2((o[j2][2] * c1 + Ocomb[r1][col])     * inv1,
                                                 (o[j2][3] * c1 + Ocomb[r1][col + 1]) * inv1);
        }
    }
}

// ============================================================
extern "C" void kernel_launch(void* const* d_in, const int* in_sizes, int n_in,
                              void* d_out, int out_size)
{
    const float* x  = (const float*)d_in[0];
    const float* Wk = (const float*)d_in[1];
    const float* Wq = (const float*)d_in[2];
    const float* Wv = (const float*)d_in[3];
    float* out = (float*)d_out;

    cudaFuncSetAttribute(proj_kernel,
                         cudaFuncAttributeMaxDynamicSharedMemorySize, SMEM_PROJ);
    cudaFuncSetAttribute(attn_kernel,
                         cudaFuncAttributeMaxDynamicSharedMemorySize, SMEM_ATTN);

    split_kernel<<<4096, 256>>>(x);
    wsplit_kernel<<<dim3(3, 32), 256>>>(Wk, Wq, Wv);
    proj_kernel<<<dim3(3, NROWS / 128), 256, SMEM_PROJ>>>();
    attn_kernel<<<256, 256, SMEM_ATTN>>>(out);
    (void)in_sizes; (void)n_in; (void)out_size;
}

// round 12
// speedup vs baseline: 1.1013x; 1.1013x over previous
#include <cuda_runtime.h>
#include <cuda_fp16.h>
#include <math_constants.h>
#include <cstdint>

#define Bsz 8
#define T   2048
#define C   1024
#define H   128
#define NROWS (Bsz * T)

// -------- gmem scratch (16B aligned) --------
__device__ __align__(16) __half g_xh[NROWS * C];
__device__ __align__(16) __half g_xl[NROWS * C];
__device__ __align__(16) __half g_wth[3 * H * C];
__device__ __align__(16) __half g_wtl[3 * H * C];
__device__ __align__(16) __half g_qh[NROWS * H];
__device__ __align__(16) __half g_ql[NROWS * H];
__device__ __align__(16) __half g_kh[NROWS * H];
__device__ __align__(16) __half g_kl[NROWS * H];
__device__ __align__(16) __half g_vth[Bsz * H * T];
__device__ __align__(16) __half g_vtl[Bsz * H * T];

// -------- helpers --------
__device__ __forceinline__ void mma16816(float* c, const unsigned* a, const unsigned* b) {
    asm volatile(
        "mma.sync.aligned.m16n8k16.row.col.f32.f16.f16.f32 "
        "{%0,%1,%2,%3}, {%4,%5,%6,%7}, {%8,%9}, {%0,%1,%2,%3};"
        : "+f"(c[0]), "+f"(c[1]), "+f"(c[2]), "+f"(c[3])
        : "r"(a[0]), "r"(a[1]), "r"(a[2]), "r"(a[3]), "r"(b[0]), "r"(b[1]));
}
__device__ __forceinline__ unsigned h2u(float x, float y) {
    __half2 h = __floats2half2_rn(x, y);
    return *reinterpret_cast<unsigned*>(&h);
}
__device__ __forceinline__ unsigned h2lo(float x, float y, unsigned hi) {
    __half2 h = *reinterpret_cast<__half2*>(&hi);
    float2 f = __half22float2(h);
    __half2 l = __floats2half2_rn(x - f.x, y - f.y);
    return *reinterpret_cast<unsigned*>(&l);
}
__device__ __forceinline__ void cpa16(uint32_t dst, const void* src) {
    asm volatile("cp.async.cg.shared.global [%0], [%1], 16;" :: "r"(dst), "l"(src));
}
#define CP_COMMIT() asm volatile("cp.async.commit_group;" ::: "memory")
#define CP_WAIT0()  asm volatile("cp.async.wait_group 0;" ::: "memory")

// ============================================================
// split_kernel: x (fp32) -> half hi/lo
// ============================================================
__global__ __launch_bounds__(256) void split_kernel(const float* __restrict__ x)
{
    const int tid = threadIdx.x;
#pragma unroll
    for (int i = 0; i < 4; i++) {
        unsigned u = blockIdx.x * 1024 + i * 256 + tid;
        float4 v = ((const float4*)x)[u];
        unsigned h0 = h2u(v.x, v.y), h1 = h2u(v.z, v.w);
        unsigned l0 = h2lo(v.x, v.y, h0), l1 = h2lo(v.z, v.w, h1);
        ((uint2*)g_xh)[u] = make_uint2(h0, h1);
        ((uint2*)g_xl)[u] = make_uint2(l0, l1);
    }
}

// ============================================================
// wsplit_kernel: W[k][n] -> W^T hi/lo [sel][n][k]
// ============================================================
__global__ __launch_bounds__(256) void wsplit_kernel(
    const float* __restrict__ Wk, const float* __restrict__ Wq,
    const float* __restrict__ Wv)
{
    __shared__ float ws[32][133];
    const int sel = blockIdx.x;
    const float* W = (sel == 0) ? Wk : (sel == 1) ? Wq : Wv;
    const int k0 = blockIdx.y * 32;
    const int tid = threadIdx.x;
#pragma unroll
    for (int i = 0; i < 16; i++) {
        int idx = tid + i * 256;
        int k = idx >> 7, n = idx & 127;
        ws[k][n] = W[(size_t)(k0 + k) * H + n];
    }
    __syncthreads();
    __half* wth = g_wth + (size_t)sel * H * C;
    __half* wtl = g_wtl + (size_t)sel * H * C;
#pragma unroll
    for (int i = 0; i < 16; i++) {
        int idx = tid + i * 256;
        int n = idx >> 5, kk = idx & 31;
        float v = ws[kk][n];
        __half h = __float2half_rn(v);
        wth[(size_t)n * C + k0 + kk] = h;
        wtl[(size_t)n * C + k0 + kk] = __float2half_rn(v - __half2float(h));
    }
}

// ============================================================
// Projection GEMM (HMMA fp16x3), cp.async double-buffered.
// ============================================================
#define PSTR 40                 // halves; 80B row stride
#define PB_ARR 10240
#define PB_SZ  40960
#define SMEM_PROJ 81920

__global__ __launch_bounds__(256, 2) void proj_kernel()
{
    extern __shared__ char smem[];
    const uint32_t sbase = (uint32_t)__cvta_generic_to_shared(smem);

    const int sel = blockIdx.x;
    const int m0 = blockIdx.y * 128;
    const int tid = threadIdx.x;
    const int w = tid >> 5, lane = tid & 31;
    const int wm = w & 3, wn = w >> 2;
    const int g = lane >> 2, t = lane & 3;

    const __half* src[4] = {
        g_xh + (size_t)m0 * C, g_xl + (size_t)m0 * C,
        g_wth + (size_t)sel * H * C, g_wtl + (size_t)sel * H * C };

    int larr[8], lrow[8], lc8[8];
#pragma unroll
    for (int i = 0; i < 8; i++) {
        int idx = tid + i * 256;
        larr[i] = idx >> 9;
        int j = idx & 511;
        lrow[i] = j >> 2;
        lc8[i]  = (j & 3) * 8;
    }

#pragma unroll
    for (int i = 0; i < 8; i++)
        cpa16(sbase + larr[i] * PB_ARR + lrow[i] * 80 + lc8[i] * 2,
              src[larr[i]] + (size_t)lrow[i] * C + lc8[i]);
    CP_COMMIT();

    float c[2][8][4];
#pragma unroll
    for (int mt = 0; mt < 2; mt++)
#pragma unroll
        for (int j = 0; j < 8; j++)
#pragma unroll
            for (int e = 0; e < 4; e++) c[mt][j][e] = 0.f;

    for (int ks = 0; ks < 32; ks++) {
        CP_WAIT0();
        __syncthreads();
        char* buf = smem + (ks & 1) * PB_SZ;
        if (ks < 31) {
            const uint32_t db = sbase + ((ks + 1) & 1) * PB_SZ;
            const int k1 = (ks + 1) * 32;
#pragma unroll
            for (int i = 0; i < 8; i++)
                cpa16(db + larr[i] * PB_ARR + lrow[i] * 80 + lc8[i] * 2,
                      src[larr[i]] + (size_t)lrow[i] * C + k1 + lc8[i]);
            CP_COMMIT();
        }
        __half (*Ah)[PSTR] = (__half(*)[PSTR])(buf);
        __half (*Al)[PSTR] = (__half(*)[PSTR])(buf + PB_ARR);
        __half (*Bh)[PSTR] = (__half(*)[PSTR])(buf + 2 * PB_ARR);
        __half (*Bl)[PSTR] = (__half(*)[PSTR])(buf + 3 * PB_ARR);

#pragma unroll
        for (int kk = 0; kk < 2; kk++) {
            const int col0 = kk * 16 + 2 * t;
            unsigned ah[2][4], al[2][4];
#pragma unroll
            for (int mt = 0; mt < 2; mt++) {
                int row = wm * 32 + mt * 16 + g;
                ah[mt][0] = *(unsigned*)&Ah[row][col0];
                ah[mt][1] = *(unsigned*)&Ah[row + 8][col0];
                ah[mt][2] = *(unsigned*)&Ah[row][col0 + 8];
                ah[mt][3] = *(unsigned*)&Ah[row + 8][col0 + 8];
                al[mt][0] = *(unsigned*)&Al[row][col0];
                al[mt][1] = *(unsigned*)&Al[row + 8][col0];
                al[mt][2] = *(unsigned*)&Al[row][col0 + 8];
                al[mt][3] = *(unsigned*)&Al[row + 8][col0 + 8];
            }
#pragma unroll
            for (int j = 0; j < 8; j++) {
                int n = wn * 64 + j * 8 + g;
                unsigned bh[2] = { *(unsigned*)&Bh[n][col0], *(unsigned*)&Bh[n][col0 + 8] };
                unsigned bl[2] = { *(unsigned*)&Bl[n][col0], *(unsigned*)&Bl[n][col0 + 8] };
#pragma unroll
                for (int mt = 0; mt < 2; mt++) {
                    mma16816(c[mt][j], ah[mt], bh);
                    mma16816(c[mt][j], ah[mt], bl);
                    mma16816(c[mt][j], al[mt], bh);
                }
            }
        }
    }

    // ---- fused split epilogue
    if (sel == 2) {
#pragma unroll
        for (int mt = 0; mt < 2; mt++)
#pragma unroll
            for (int j = 0; j < 8; j++) {
                int row0 = m0 + wm * 32 + mt * 16 + g;
                int col = wn * 64 + j * 8 + 2 * t;
#pragma unroll
                for (int e = 0; e < 4; e++) {
                    int row = row0 + (e >> 1) * 8;
                    int n = col + (e & 1);
                    float val = c[mt][j][e];
                    __half h = __float2half_rn(val);
                    size_t a = ((size_t)(row >> 11) * H + n) * T + (row & 2047);
                    g_vth[a] = h;
                    g_vtl[a] = __float2half_rn(val - __half2float(h));
                }
            }
    } else {
        __half* ghi = (sel == 0) ? g_kh : g_qh;
        __half* glo = (sel == 0) ? g_kl : g_ql;
        const float sc = (sel == 1) ? 32.f : 1.f;
#pragma unroll
        for (int mt = 0; mt < 2; mt++)
#pragma unroll
            for (int j = 0; j < 8; j++) {
                int row0 = m0 + wm * 32 + mt * 16 + g;
                int col = wn * 64 + j * 8 + 2 * t;
#pragma unroll
                for (int hr = 0; hr < 2; hr++) {
                    int row = row0 + hr * 8;
                    float v0 = c[mt][j][hr * 2] * sc;
                    float v1 = c[mt][j][hr * 2 + 1] * sc;
                    unsigned hi = h2u(v0, v1);
                    unsigned lo = h2lo(v0, v1, hi);
                    *(unsigned*)(ghi + (size_t)row * H + col) = hi;
                    *(unsigned*)(glo + (size_t)row * H + col) = lo;
                }
            }
    }
}

// ============================================================
// Flash attention (HMMA), causal. S = fp16x3; PV = fp16(P) x V hi/lo
// (2-pass: exact-P-rounding scheme, P_lo term dropped within error budget).
// Warp-local split-K softmax, cp.async double-buffered KV.
// ============================================================
#define ASTR 136
#define VSTR 72

#define A_QH   0
#define A_QL   17408
#define A_KV0  34816
#define KV_KH  0
#define KV_KL  17408
#define KV_VTH 34816
#define KV_VTL 53248
#define KV_SZ  71680
#define A_PM   178176
#define A_PL   178688
#define SMEM_ATTN 179200

__global__ __launch_bounds__(256, 1) void attn_kernel(float* __restrict__ out)
{
    extern __shared__ char smem[];
    const uint32_t sbase = (uint32_t)__cvta_generic_to_shared(smem);

    const int tid = threadIdx.x;
    const int w = tid >> 5, lane = tid & 31;
    const int wm = w & 3, wn = w >> 2;
    const int g = lane >> 2, t = lane & 3;
    const int bx = blockIdx.x;
    const int b = bx & 7;
    const int qt = 31 - (bx >> 3);          // LPT

    const __half* QHg = g_qh + ((size_t)b * T + (size_t)qt * 64) * H;
    const __half* QLg = g_ql + ((size_t)b * T + (size_t)qt * 64) * H;
    const __half* KHg = g_kh + (size_t)b * T * H;
    const __half* KLg = g_kl + (size_t)b * T * H;
    const __half* VHg = g_vth + (size_t)b * H * T;
    const __half* VLg = g_vtl + (size_t)b * H * T;

    // ---- prologue: Q + KV tile 0 via cp.async
#pragma unroll
    for (int i = 0; i < 4; i++) {
        int idx = tid + i * 256;
        int row = idx >> 4, c8 = (idx & 15) * 8;
        cpa16(sbase + A_QH + row * 272 + c8 * 2, QHg + (size_t)row * H + c8);
        cpa16(sbase + A_QL + row * 272 + c8 * 2, QLg + (size_t)row * H + c8);
    }
    {
        const uint32_t kb = sbase + A_KV0;
#pragma unroll
        for (int i = 0; i < 4; i++) {
            int idx = tid + i * 256;
            int row = idx >> 4, c8 = (idx & 15) * 8;
            cpa16(kb + KV_KH + row * 272 + c8 * 2, KHg + (size_t)row * H + c8);
            cpa16(kb + KV_KL + row * 272 + c8 * 2, KLg + (size_t)row * H + c8);
            int vr = idx >> 3, v8 = (idx & 7) * 8;
            cpa16(kb + KV_VTH + vr * 144 + v8 * 2, VHg + (size_t)vr * T + v8);
            cpa16(kb + KV_VTL + vr * 144 + v8 * 2, VLg + (size_t)vr * T + v8);
        }
    }
    CP_COMMIT();

    __half (*QH)[ASTR] = (__half(*)[ASTR])(smem + A_QH);
    __half (*QL)[ASTR] = (__half(*)[ASTR])(smem + A_QL);

    const int r0 = wm * 16 + g, r1 = r0 + 8;
    float m[2] = {-1e30f, -1e30f}, l[2] = {0.f, 0.f};
    float o[16][4];
#pragma unroll
    for (int j = 0; j < 16; j++)
#pragma unroll
        for (int e = 0; e < 4; e++) o[j][e] = 0.f;

    for (int kt = 0; kt <= qt; kt++) {
        CP_WAIT0();
        __syncthreads();
        char* kv = smem + A_KV0 + (kt & 1) * KV_SZ;
        if (kt < qt) {
            const uint32_t kb = sbase + A_KV0 + ((kt + 1) & 1) * KV_SZ;
            const size_t koff = (size_t)(kt + 1) * 64;
#pragma unroll
            for (int i = 0; i < 4; i++) {
                int idx = tid + i * 256;
                int row = idx >> 4, c8 = (idx & 15) * 8;
                cpa16(kb + KV_KH + row * 272 + c8 * 2, KHg + (koff + row) * H + c8);
                cpa16(kb + KV_KL + row * 272 + c8 * 2, KLg + (koff + row) * H + c8);
                int vr = idx >> 3, v8 = (idx & 7) * 8;
                cpa16(kb + KV_VTH + vr * 144 + v8 * 2, VHg + (size_t)vr * T + koff + v8);
                cpa16(kb + KV_VTL + vr * 144 + v8 * 2, VLg + (size_t)vr * T + koff + v8);
            }
            CP_COMMIT();
        }
        __half (*KH)[ASTR]  = (__half(*)[ASTR])(kv + KV_KH);
        __half (*KL)[ASTR]  = (__half(*)[ASTR])(kv + KV_KL);
        __half (*VTH)[VSTR] = (__half(*)[VSTR])(kv + KV_VTH);
        __half (*VTL)[VSTR] = (__half(*)[VSTR])(kv + KV_VTL);

        // ---- S = Q K^T (3-pass Markidis)
        float s[4][4];
#pragma unroll
        for (int j = 0; j < 4; j++)
#pragma unroll
            for (int e = 0; e < 4; e++) s[j][e] = 0.f;

#pragma unroll
        for (int kk = 0; kk < 8; kk++) {
            const int col0 = kk * 16 + 2 * t;
            unsigned ah[4], al[4];
            ah[0] = *(unsigned*)&QH[r0][col0];
            ah[1] = *(unsigned*)&QH[r1][col0];
            ah[2] = *(unsigned*)&QH[r0][col0 + 8];
            ah[3] = *(unsigned*)&QH[r1][col0 + 8];
            al[0] = *(unsigned*)&QL[r0][col0];
            al[1] = *(unsigned*)&QL[r1][col0];
            al[2] = *(unsigned*)&QL[r0][col0 + 8];
            al[3] = *(unsigned*)&QL[r1][col0 + 8];
#pragma unroll
            for (int j = 0; j < 4; j++) {
                int n = wn * 32 + j * 8 + g;
                unsigned bh[2] = { *(unsigned*)&KH[n][col0], *(unsigned*)&KH[n][col0 + 8] };
                unsigned bl[2] = { *(unsigned*)&KL[n][col0], *(unsigned*)&KL[n][col0 + 8] };
                mma16816(s[j], ah, bh);
                mma16816(s[j], ah, bl);
                mma16816(s[j], al, bh);
            }
        }

        if (kt == qt) {
#pragma unroll
            for (int j = 0; j < 4; j++) {
                int cl = wn * 32 + j * 8 + 2 * t;
                if (cl     > r0) s[j][0] = -3e38f;
                if (cl + 1 > r0) s[j][1] = -3e38f;
                if (cl     > r1) s[j][2] = -3e38f;
                if (cl + 1 > r1) s[j][3] = -3e38f;
            }
        }

        // ---- warp-local online softmax
        float mx0 = -3e38f, mx1 = -3e38f;
#pragma unroll
        for (int j = 0; j < 4; j++) {
            mx0 = fmaxf(mx0, fmaxf(s[j][0], s[j][1]));
            mx1 = fmaxf(mx1, fmaxf(s[j][2], s[j][3]));
        }
        mx0 = fmaxf(mx0, __shfl_xor_sync(0xFFFFFFFFu, mx0, 1));
        mx0 = fmaxf(mx0, __shfl_xor_sync(0xFFFFFFFFu, mx0, 2));
        mx1 = fmaxf(mx1, __shfl_xor_sync(0xFFFFFFFFu, mx1, 1));
        mx1 = fmaxf(mx1, __shfl_xor_sync(0xFFFFFFFFu, mx1, 2));

        float mn0 = fmaxf(m[0], mx0);
        float mn1 = fmaxf(m[1], mx1);
        float al0 = __expf(m[0] - mn0);
        float al1 = __expf(m[1] - mn1);

        float sum0 = 0.f, sum1 = 0.f;
#pragma unroll
        for (int j = 0; j < 4; j++) {
            s[j][0] = __expf(s[j][0] - mn0);
            s[j][1] = __expf(s[j][1] - mn0);
            s[j][2] = __expf(s[j][2] - mn1);
            s[j][3] = __expf(s[j][3] - mn1);
            sum0 += s[j][0] + s[j][1];
            sum1 += s[j][2] + s[j][3];
        }
        sum0 += __shfl_xor_sync(0xFFFFFFFFu, sum0, 1);
        sum0 += __shfl_xor_sync(0xFFFFFFFFu, sum0, 2);
        sum1 += __shfl_xor_sync(0xFFFFFFFFu, sum1, 1);
        sum1 += __shfl_xor_sync(0xFFFFFFFFu, sum1, 2);

        l[0] = l[0] * al0 + sum0;
        l[1] = l[1] * al1 + sum1;
        m[0] = mn0; m[1] = mn1;

#pragma unroll
        for (int j = 0; j < 16; j++) {
            o[j][0] *= al0; o[j][1] *= al0;
            o[j][2] *= al1; o[j][3] *= al1;
        }
        // ---- O += fp16(P) * (V_hi + V_lo)  (2-pass PV)
#pragma unroll
        for (int kk2 = 0; kk2 < 2; kk2++) {
            unsigned aph[4];
            aph[0] = h2u(s[2*kk2][0], s[2*kk2][1]);
            aph[1] = h2u(s[2*kk2][2], s[2*kk2][3]);
            aph[2] = h2u(s[2*kk2+1][0], s[2*kk2+1][1]);
            aph[3] = h2u(s[2*kk2+1][2], s[2*kk2+1][3]);
            const int col = wn * 32 + kk2 * 16 + 2 * t;
#pragma unroll
            for (int j2 = 0; j2 < 16; j2++) {
                int h = j2 * 8 + g;
                unsigned bh[2] = { *(unsigned*)&VTH[h][col], *(unsigned*)&VTH[h][col + 8] };
                unsigned bl[2] = { *(unsigned*)&VTL[h][col], *(unsigned*)&VTL[h][col + 8] };
                mma16816(o[j2], aph, bh);
                mma16816(o[j2], aph, bl);
            }
        }
    }

    // ---- final split-K combine across the two wn halves
    float* pm = (float*)(smem + A_PM);
    float* pl = (float*)(smem + A_PL);
    __syncthreads();
    if (t == 0) {
        pm[wn * 64 + r0] = m[0]; pm[wn * 64 + r1] = m[1];
        pl[wn * 64 + r0] = l[0]; pl[wn * 64 + r1] = l[1];
    }
    __syncthreads();
    float M0 = fmaxf(pm[r0], pm[64 + r0]);
    float M1 = fmaxf(pm[r1], pm[64 + r1]);
    float L0 = pl[r0] * __expf(pm[r0] - M0) + pl[64 + r0] * __expf(pm[64 + r0] - M0);
    float L1 = pl[r1] * __expf(pm[r1] - M1) + pl[64 + r1] * __expf(pm[64 + r1] - M1);
    float c0 = __expf(m[0] - M0);
    float c1 = __expf(m[1] - M1);

    float (*Ocomb)[132] = (float(*)[132])(smem + A_QH);
    if (wn == 1) {
#pragma unroll
        for (int j2 = 0; j2 < 16; j2++) {
            int col = j2 * 8 + 2 * t;
            *(float2*)&Ocomb[r0][col] = make_float2(o[j2][0] * c0, o[j2][1] * c0);
            *(float2*)&Ocomb[r1][col] = make_float2(o[j2][2] * c1, o[j2][3] * c1);
        }
    }
    __syncthreads();
    if (wn == 0) {
        const float inv0 = 1.f / L0, inv1 = 1.f / L1;
        float* out0 = out + ((size_t)b * T + (size_t)qt * 64 + r0) * H;
        float* out1 = out + ((size_t)b * T + (size_t)qt * 64 + r1) * H;
#pragma unroll
        for (int j2 = 0; j2 < 16; j2++) {
            int col = j2 * 8 + 2 * t;
            *(float2*)(out0 + col) = make_float2((o[j2][0] * c0 + Ocomb[r0][col])     * inv0,
                                                 (o[j2][1] * c0 + Ocomb[r0][col + 1]) * inv0);
            *(float2*)(out1 + col) = make_float2((o[j2][2] * c1 + Ocomb[r1][col])     * inv1,
                                                 (o[j2][3] * c1 + Ocomb[r1][col + 1]) * inv1);
        }
    }
}

// ============================================================
extern "C" void kernel_launch(void* const* d_in, const int* in_sizes, int n_in,
                              void* d_out, int out_size)
{
    const float* x  = (const float*)d_in[0];
    const float* Wk = (const float*)d_in[1];
    const float* Wq = (const float*)d_in[2];
    const float* Wv = (const float*)d_in[3];
    float* out = (float*)d_out;

    cudaFuncSetAttribute(proj_kernel,
                         cudaFuncAttributeMaxDynamicSharedMemorySize, SMEM_PROJ);
    cudaFuncSetAttribute(attn_kernel,
                         cudaFuncAttributeMaxDynamicSharedMemorySize, SMEM_ATTN);

    split_kernel<<<4096, 256>>>(x);
    wsplit_kernel<<<dim3(3, 32), 256>>>(Wk, Wq, Wv);
    proj_kernel<<<dim3(3, NROWS / 128), 256, SMEM_PROJ>>>();
    attn_kernel<<<256, 256, SMEM_ATTN>>>(out);
    (void)in_sizes; (void)n_in; (void)out_size;
}